// round 2
// baseline (speedup 1.0000x reference)
#include <cuda_runtime.h>
#include <cstdint>
#include <cstddef>

// Problem constants
#define cT   1024
#define cB   512
#define cOBS 64
#define cH   128
#define cA   16
#define cG   384          // 3*H
#define cTB  (cT * cB)    // 524288

// Scratch (allocations are forbidden -> __device__ globals)
__device__ float g_xi[(size_t)cTB * cG];   // [T*B, 384] input-side gate pre-activations
__device__ float g_y[(size_t)cTB * cH];    // [T*B, 128] GRU outputs

// ---------------------------------------------------------------------------
// Kernel 1: fused embedding + input gate projection
//   emb = relu(obs @ W_emb + b_emb)   [64 rows/block]
//   xi  = emb @ Wi + bi               (384 cols, in 3 chunks of 128)
// 256 threads, each computes an 8x4 register tile.
// ---------------------------------------------------------------------------
__global__ __launch_bounds__(256) void k_embed_xi(
    const float* __restrict__ obs, const float* __restrict__ W_emb,
    const float* __restrict__ b_emb, const float* __restrict__ Wi,
    const float* __restrict__ bi)
{
    extern __shared__ float sm[];
    float* s_obs = sm;                   // 64*64   = 4096
    float* s_We  = s_obs + 64 * 64;      // 64*128  = 8192
    float* s_emb = s_We + 64 * 128;      // 64*132  = 8448 (padded pitch)
    float* s_w   = s_emb + 64 * 132;     // 128*128 = 16384

    const int tid  = threadIdx.x;
    const int lane = tid & 31;
    const int wrp  = tid >> 5;           // 0..7
    const int c0   = lane * 4;
    const int r0   = wrp * 8;
    const size_t row0 = (size_t)blockIdx.x * 64;

    for (int i = tid; i < 64 * 64; i += 256)  s_obs[i] = obs[row0 * cOBS + i];
    for (int i = tid; i < 64 * 128; i += 256) s_We[i]  = W_emb[i];
    __syncthreads();

    float acc[8][4];
#pragma unroll
    for (int r = 0; r < 8; r++) { acc[r][0] = acc[r][1] = acc[r][2] = acc[r][3] = 0.f; }

#pragma unroll 4
    for (int k = 0; k < 64; k++) {
        float4 w = *reinterpret_cast<const float4*>(&s_We[k * 128 + c0]);
#pragma unroll
        for (int r = 0; r < 8; r++) {
            float a = s_obs[(r0 + r) * 64 + k];
            acc[r][0] += a * w.x; acc[r][1] += a * w.y;
            acc[r][2] += a * w.z; acc[r][3] += a * w.w;
        }
    }
    {
        float4 be = *reinterpret_cast<const float4*>(&b_emb[c0]);
#pragma unroll
        for (int r = 0; r < 8; r++) {
            float* d = &s_emb[(r0 + r) * 132 + c0];
            d[0] = fmaxf(acc[r][0] + be.x, 0.f);
            d[1] = fmaxf(acc[r][1] + be.y, 0.f);
            d[2] = fmaxf(acc[r][2] + be.z, 0.f);
            d[3] = fmaxf(acc[r][3] + be.w, 0.f);
        }
    }
    __syncthreads();

    for (int chunk = 0; chunk < 3; chunk++) {
        for (int i = tid; i < 128 * 128; i += 256) {
            int k = i >> 7, c = i & 127;
            s_w[i] = Wi[k * cG + chunk * 128 + c];
        }
        __syncthreads();

#pragma unroll
        for (int r = 0; r < 8; r++) { acc[r][0] = acc[r][1] = acc[r][2] = acc[r][3] = 0.f; }
#pragma unroll 4
        for (int k = 0; k < 128; k++) {
            float4 w = *reinterpret_cast<const float4*>(&s_w[k * 128 + c0]);
#pragma unroll
            for (int r = 0; r < 8; r++) {
                float a = s_emb[(r0 + r) * 132 + k];
                acc[r][0] += a * w.x; acc[r][1] += a * w.y;
                acc[r][2] += a * w.z; acc[r][3] += a * w.w;
            }
        }
        float4 bv = *reinterpret_cast<const float4*>(&bi[chunk * 128 + c0]);
#pragma unroll
        for (int r = 0; r < 8; r++) {
            float4 o;
            o.x = acc[r][0] + bv.x; o.y = acc[r][1] + bv.y;
            o.z = acc[r][2] + bv.z; o.w = acc[r][3] + bv.w;
            *reinterpret_cast<float4*>(&g_xi[(row0 + r0 + r) * cG + chunk * 128 + c0]) = o;
        }
        __syncthreads();
    }
}

// ---------------------------------------------------------------------------
// Kernel 2: GRU scan. Batch rows are independent -> 128 persistent blocks,
// 4 rows each, Wh (192KB fp32) resident in shared memory, all 1024 steps
// block-local. 384 threads: thread j owns gate column j for all 4 rows.
// dones is read as int32 (bool upcast by the harness; also bit-correct for
// float32: 0.0f == 0x0, 1.0f == 0x3f800000 != 0).
// ---------------------------------------------------------------------------
__global__ __launch_bounds__(384) void k_scan(
    const float* __restrict__ h0,
    const int* __restrict__ dones,
    const float* __restrict__ Wh,
    const float* __restrict__ bh_n,
    float* __restrict__ out_hidden)
{
    extern __shared__ float sm[];
    float* Wh_s = sm;                    // 128*384 = 49152
    float* h_s  = Wh_s + 49152;          // 4*128   = 512
    float* hh_s = h_s + 512;             // 4*384   = 1536
    float* xn_s = hh_s + 1536;           // 4*128   = 512
    float* bh_s = xn_s + 512;            // 128

    const int tid = threadIdx.x;
    const int rowbase = blockIdx.x * 4;

    for (int i = tid; i < 49152; i += 384) Wh_s[i] = Wh[i];
    if (tid < 128) bh_s[tid] = bh_n[tid];
    {
        int d0[4];
#pragma unroll
        for (int r = 0; r < 4; r++) d0[r] = dones[rowbase + r];
        for (int i = tid; i < 512; i += 384)
            h_s[i] = (d0[i >> 7] != 0) ? 0.f : h0[rowbase * cH + i];
    }
    __syncthreads();

    for (int t = 0; t < cT; t++) {
        // Prefetch xi column for this step (latency hidden behind the GEMM)
        float xiv[4];
        {
            const float* xp = &g_xi[((size_t)t * cB + rowbase) * cG + tid];
#pragma unroll
            for (int r = 0; r < 4; r++) xiv[r] = xp[(size_t)r * cG];
        }
        int dn[4];
        if (t + 1 < cT) {
#pragma unroll
            for (int r = 0; r < 4; r++) dn[r] = dones[(size_t)(t + 1) * cB + rowbase + r];
        } else {
            dn[0] = dn[1] = dn[2] = dn[3] = 0;
        }

        // hh[r][tid] = sum_k h[r][k] * Wh[k][tid]
        float acc[4] = {0.f, 0.f, 0.f, 0.f};
#pragma unroll 2
        for (int k = 0; k < 128; k += 4) {
            float4 hv[4];
#pragma unroll
            for (int r = 0; r < 4; r++)
                hv[r] = *reinterpret_cast<const float4*>(&h_s[r * 128 + k]);
#pragma unroll
            for (int kk = 0; kk < 4; kk++) {
                float w = Wh_s[(k + kk) * cG + tid];
                acc[0] += reinterpret_cast<const float*>(&hv[0])[kk] * w;
                acc[1] += reinterpret_cast<const float*>(&hv[1])[kk] * w;
                acc[2] += reinterpret_cast<const float*>(&hv[2])[kk] * w;
                acc[3] += reinterpret_cast<const float*>(&hv[3])[kk] * w;
            }
        }
        if (tid < 256) {
            // r,z gates: fold in xi now
#pragma unroll
            for (int r = 0; r < 4; r++) hh_s[r * cG + tid] = acc[r] + xiv[r];
        } else {
            const int m = tid - 256;
#pragma unroll
            for (int r = 0; r < 4; r++) {
                hh_s[r * cG + tid] = acc[r];      // hn (keep separate: n-gate needs r*(hn+bh))
                xn_s[r * 128 + m]  = xiv[r];      // xn
            }
        }
        __syncthreads();

        // Gate math + state update: 512 items over 384 threads
        for (int i = tid; i < 512; i += 384) {
            const int r = i >> 7, m = i & 127;
            float pre_r = hh_s[r * cG + m];
            float pre_z = hh_s[r * cG + 128 + m];
            float hn    = hh_s[r * cG + 256 + m];
            float rg = 1.f / (1.f + expf(-pre_r));
            float zg = 1.f / (1.f + expf(-pre_z));
            float ng = tanhf(xn_s[r * 128 + m] + rg * (hn + bh_s[m]));
            float hprev = h_s[i];
            float hnew  = (1.f - zg) * ng + zg * hprev;
            g_y[((size_t)t * cB + rowbase + r) * cH + m] = hnew;
            if (t == cT - 1) out_hidden[(rowbase + r) * cH + m] = hnew;
            h_s[i] = (dn[r] != 0) ? 0.f : hnew;   // apply next step's done-reset now
        }
        __syncthreads();
    }
}

// ---------------------------------------------------------------------------
// Kernel 3: actor + critic heads. 64 rows/block, 256 threads.
// ---------------------------------------------------------------------------
__global__ __launch_bounds__(256) void k_heads(
    const float* __restrict__ Wa1, const float* __restrict__ ba1,
    const float* __restrict__ Wa2, const float* __restrict__ ba2,
    const float* __restrict__ Wc1, const float* __restrict__ bc1,
    const float* __restrict__ Wc2, const float* __restrict__ bc2,
    float* __restrict__ out_logits, float* __restrict__ out_v)
{
    extern __shared__ float sm[];
    float* s_y   = sm;                   // 64*132  = 8448
    float* s_w   = s_y + 8448;           // 128*128 = 16384
    float* s_h   = s_w + 16384;          // 64*132  = 8448
    float* s_w2  = s_h + 8448;           // 128*16  = 2048
    float* s_wc2 = s_w2 + 2048;          // 128

    const int tid  = threadIdx.x;
    const int lane = tid & 31;
    const int wrp  = tid >> 5;
    const int c0   = lane * 4;
    const int r0   = wrp * 8;
    const size_t row0 = (size_t)blockIdx.x * 64;

    for (int i = tid; i < 64 * 128; i += 256) {
        int r = i >> 7, k = i & 127;
        s_y[r * 132 + k] = g_y[row0 * cH + i];
    }
    for (int i = tid; i < 128 * 128; i += 256) s_w[i]  = Wa1[i];
    for (int i = tid; i < 128 * 16; i += 256)  s_w2[i] = Wa2[i];
    if (tid < 128) s_wc2[tid] = Wc2[tid];
    __syncthreads();

    float acc[8][4];

    // actor layer 1: a1 = relu(y @ Wa1 + ba1)
#pragma unroll
    for (int r = 0; r < 8; r++) { acc[r][0] = acc[r][1] = acc[r][2] = acc[r][3] = 0.f; }
#pragma unroll 4
    for (int k = 0; k < 128; k++) {
        float4 w = *reinterpret_cast<const float4*>(&s_w[k * 128 + c0]);
#pragma unroll
        for (int r = 0; r < 8; r++) {
            float a = s_y[(r0 + r) * 132 + k];
            acc[r][0] += a * w.x; acc[r][1] += a * w.y;
            acc[r][2] += a * w.z; acc[r][3] += a * w.w;
        }
    }
    {
        float4 bv = *reinterpret_cast<const float4*>(&ba1[c0]);
#pragma unroll
        for (int r = 0; r < 8; r++) {
            float* d = &s_h[(r0 + r) * 132 + c0];
            d[0] = fmaxf(acc[r][0] + bv.x, 0.f);
            d[1] = fmaxf(acc[r][1] + bv.y, 0.f);
            d[2] = fmaxf(acc[r][2] + bv.z, 0.f);
            d[3] = fmaxf(acc[r][3] + bv.w, 0.f);
        }
    }
    __syncthreads();

    // logits = a1 @ Wa2 + ba2    (thread: 1 row x 4 cols)
    {
        const int lrow = tid >> 2;
        const int cg   = (tid & 3) * 4;
        float a4[4] = {0.f, 0.f, 0.f, 0.f};
#pragma unroll 4
        for (int k = 0; k < 128; k++) {
            float a  = s_h[lrow * 132 + k];
            float4 w = *reinterpret_cast<const float4*>(&s_w2[k * 16 + cg]);
            a4[0] += a * w.x; a4[1] += a * w.y; a4[2] += a * w.z; a4[3] += a * w.w;
        }
        float4 bv = *reinterpret_cast<const float4*>(&ba2[cg]);
        float4 o;
        o.x = a4[0] + bv.x; o.y = a4[1] + bv.y; o.z = a4[2] + bv.z; o.w = a4[3] + bv.w;
        *reinterpret_cast<float4*>(&out_logits[(row0 + lrow) * cA + cg]) = o;
    }
    __syncthreads();

    // critic layer 1
    for (int i = tid; i < 128 * 128; i += 256) s_w[i] = Wc1[i];
    __syncthreads();
#pragma unroll
    for (int r = 0; r < 8; r++) { acc[r][0] = acc[r][1] = acc[r][2] = acc[r][3] = 0.f; }
#pragma unroll 4
    for (int k = 0; k < 128; k++) {
        float4 w = *reinterpret_cast<const float4*>(&s_w[k * 128 + c0]);
#pragma unroll
        for (int r = 0; r < 8; r++) {
            float a = s_y[(r0 + r) * 132 + k];
            acc[r][0] += a * w.x; acc[r][1] += a * w.y;
            acc[r][2] += a * w.z; acc[r][3] += a * w.w;
        }
    }
    {
        float4 bv = *reinterpret_cast<const float4*>(&bc1[c0]);
#pragma unroll
        for (int r = 0; r < 8; r++) {
            float* d = &s_h[(r0 + r) * 132 + c0];
            d[0] = fmaxf(acc[r][0] + bv.x, 0.f);
            d[1] = fmaxf(acc[r][1] + bv.y, 0.f);
            d[2] = fmaxf(acc[r][2] + bv.z, 0.f);
            d[3] = fmaxf(acc[r][3] + bv.w, 0.f);
        }
    }
    __syncthreads();

    // value = c1 @ Wc2 + bc2
    if (tid < 64) {
        float a = 0.f;
#pragma unroll 4
        for (int k = 0; k < 128; k++) a += s_h[tid * 132 + k] * s_wc2[k];
        out_v[row0 + tid] = a + bc2[0];
    }
}

// ---------------------------------------------------------------------------
extern "C" void kernel_launch(void* const* d_in, const int* in_sizes, int n_in,
                              void* d_out, int out_size)
{
    const float* hidden = (const float*)d_in[0];
    const float* obs    = (const float*)d_in[1];
    const int*   dones  = (const int*)d_in[2];
    const float* W_emb  = (const float*)d_in[3];
    const float* b_emb  = (const float*)d_in[4];
    const float* Wi     = (const float*)d_in[5];
    const float* bi     = (const float*)d_in[6];
    const float* Wh     = (const float*)d_in[7];
    const float* bh_n   = (const float*)d_in[8];
    const float* Wa1    = (const float*)d_in[9];
    const float* ba1    = (const float*)d_in[10];
    const float* Wa2    = (const float*)d_in[11];
    const float* ba2    = (const float*)d_in[12];
    const float* Wc1    = (const float*)d_in[13];
    const float* bc1    = (const float*)d_in[14];
    const float* Wc2    = (const float*)d_in[15];
    const float* bc2    = (const float*)d_in[16];

    float* out        = (float*)d_out;
    float* out_hidden = out;                                   // [B,H]
    float* out_logits = out + (size_t)cB * cH;                 // [T,B,A]
    float* out_v      = out_logits + (size_t)cTB * cA;         // [T,B]

    const int sm1 = (64 * 64 + 64 * 128 + 64 * 132 + 128 * 128) * (int)sizeof(float);
    const int sm2 = (49152 + 512 + 1536 + 512 + 128) * (int)sizeof(float);
    const int sm3 = (8448 + 16384 + 8448 + 2048 + 128) * (int)sizeof(float);
    cudaFuncSetAttribute(k_embed_xi, cudaFuncAttributeMaxDynamicSharedMemorySize, sm1);
    cudaFuncSetAttribute(k_scan,     cudaFuncAttributeMaxDynamicSharedMemorySize, sm2);
    cudaFuncSetAttribute(k_heads,    cudaFuncAttributeMaxDynamicSharedMemorySize, sm3);

    k_embed_xi<<<cTB / 64, 256, sm1>>>(obs, W_emb, b_emb, Wi, bi);
    k_scan<<<cB / 4, 384, sm2>>>(hidden, dones, Wh, bh_n, out_hidden);
    k_heads<<<cTB / 64, 256, sm3>>>(Wa1, ba1, Wa2, ba2, Wc1, bc1, Wc2, bc2,
                                    out_logits, out_v);
}

// round 5
// speedup vs baseline: 1.2331x; 1.2331x over previous
#include <cuda_runtime.h>
#include <cstdint>
#include <cstddef>

// Problem constants
#define cT   1024
#define cB   512
#define cOBS 64
#define cH   128
#define cA   16
#define cG   384          // 3*H
#define cTB  (cT * cB)    // 524288

typedef unsigned long long ull;

// Scratch (allocations forbidden -> __device__ globals)
__device__ float g_xi[(size_t)cTB * cG];   // [T*B, 384]
__device__ float g_y[(size_t)cTB * cH];    // [T*B, 128]

// Packed fp32 FMA: d = a*b + d elementwise on (lo,hi) pairs. SASS: FFMA2.
__device__ __forceinline__ void ffma2(ull& d, ull a, ull b) {
    asm("fma.rn.f32x2 %0, %1, %2, %0;" : "+l"(d) : "l"(a), "l"(b));
}
__device__ __forceinline__ float f2lo(ull v) { return __uint_as_float((unsigned)v); }
__device__ __forceinline__ float f2hi(ull v) { return __uint_as_float((unsigned)(v >> 32)); }
__device__ __forceinline__ float f2sum(ull v) { return f2lo(v) + f2hi(v); }

// ---------------------------------------------------------------------------
// Kernel 1: emb = relu(obs @ W_emb + b_emb); xi = emb @ Wi + bi.
// 128 rows/block, 512 threads, FFMA2 with K-pair packing.
// Weights staged k-pair interleaved: s_w[(k>>1)*256 + c*2 + (k&1)].
// ---------------------------------------------------------------------------
__global__ __launch_bounds__(512) void k_embed_xi(
    const float* __restrict__ obs, const float* __restrict__ W_emb,
    const float* __restrict__ b_emb, const float* __restrict__ Wi,
    const float* __restrict__ bi)
{
    extern __shared__ float sm[];
    float* s_obs = sm;                    // 128*64  = 8192
    float* s_emb = sm + 8192;             // 128*128 = 16384
    float* s_w   = sm + 8192 + 16384;     // 16384 (interleaved weight chunk)

    const int tid  = threadIdx.x;
    const int lane = tid & 31;
    const int wrp  = tid >> 5;            // 0..15
    const int c0   = lane * 4;
    const int r0   = wrp * 8;
    const size_t row0 = (size_t)blockIdx.x * 128;

    for (int i = tid; i < 128 * 64 / 4; i += 512)
        reinterpret_cast<float4*>(s_obs)[i] =
            reinterpret_cast<const float4*>(obs + row0 * cOBS)[i];
    for (int i = tid; i < 64 * 128; i += 512) {
        int k = i >> 7, c = i & 127;
        s_w[(k >> 1) * 256 + c * 2 + (k & 1)] = W_emb[i];
    }
    __syncthreads();

    ull acc[8][4];

    // ---- emb GEMM: K=64 (32 k-pairs) ----
#pragma unroll
    for (int r = 0; r < 8; r++) { acc[r][0] = acc[r][1] = acc[r][2] = acc[r][3] = 0ull; }
#pragma unroll 8
    for (int kp = 0; kp < 32; kp++) {
        ulonglong2 wA = *reinterpret_cast<const ulonglong2*>(&s_w[kp * 256 + c0 * 2]);
        ulonglong2 wB = *reinterpret_cast<const ulonglong2*>(&s_w[kp * 256 + c0 * 2 + 4]);
#pragma unroll
        for (int r = 0; r < 8; r++) {
            ull a2 = *reinterpret_cast<const ull*>(&s_obs[(r0 + r) * 64 + kp * 2]);
            ffma2(acc[r][0], a2, wA.x); ffma2(acc[r][1], a2, wA.y);
            ffma2(acc[r][2], a2, wB.x); ffma2(acc[r][3], a2, wB.y);
        }
    }
    __syncthreads();   // s_w reads done before restage

    {
        float4 be = *reinterpret_cast<const float4*>(&b_emb[c0]);
#pragma unroll
        for (int r = 0; r < 8; r++) {
            float* d = &s_emb[(r0 + r) * 128 + c0];
            d[0] = fmaxf(f2sum(acc[r][0]) + be.x, 0.f);
            d[1] = fmaxf(f2sum(acc[r][1]) + be.y, 0.f);
            d[2] = fmaxf(f2sum(acc[r][2]) + be.z, 0.f);
            d[3] = fmaxf(f2sum(acc[r][3]) + be.w, 0.f);
        }
    }

    // ---- xi GEMM: 3 chunks of 128 cols, K=128 (64 k-pairs) ----
    for (int chunk = 0; chunk < 3; chunk++) {
        for (int i = tid; i < 128 * 128; i += 512) {
            int k = i >> 7, c = i & 127;
            s_w[(k >> 1) * 256 + c * 2 + (k & 1)] = Wi[k * cG + chunk * 128 + c];
        }
        __syncthreads();

#pragma unroll
        for (int r = 0; r < 8; r++) { acc[r][0] = acc[r][1] = acc[r][2] = acc[r][3] = 0ull; }
#pragma unroll 8
        for (int kp = 0; kp < 64; kp++) {
            ulonglong2 wA = *reinterpret_cast<const ulonglong2*>(&s_w[kp * 256 + c0 * 2]);
            ulonglong2 wB = *reinterpret_cast<const ulonglong2*>(&s_w[kp * 256 + c0 * 2 + 4]);
#pragma unroll
            for (int r = 0; r < 8; r++) {
                ull a2 = *reinterpret_cast<const ull*>(&s_emb[(r0 + r) * 128 + kp * 2]);
                ffma2(acc[r][0], a2, wA.x); ffma2(acc[r][1], a2, wA.y);
                ffma2(acc[r][2], a2, wB.x); ffma2(acc[r][3], a2, wB.y);
            }
        }
        float4 bv = *reinterpret_cast<const float4*>(&bi[chunk * 128 + c0]);
#pragma unroll
        for (int r = 0; r < 8; r++) {
            float4 o;
            o.x = f2sum(acc[r][0]) + bv.x; o.y = f2sum(acc[r][1]) + bv.y;
            o.z = f2sum(acc[r][2]) + bv.z; o.w = f2sum(acc[r][3]) + bv.w;
            *reinterpret_cast<float4*>(&g_xi[(row0 + r0 + r) * cG + chunk * 128 + c0]) = o;
        }
        __syncthreads();
    }
}

// ---------------------------------------------------------------------------
// Kernel 2: GRU scan. 128 persistent blocks x 4 batch rows, Wh resident in
// smem (k-pair interleaved: Wh_s[(k>>1)*768 + c*2 + (k&1)]). FFMA2 mainloop.
// ---------------------------------------------------------------------------
__global__ __launch_bounds__(384) void k_scan(
    const float* __restrict__ h0,
    const int* __restrict__ dones,
    const float* __restrict__ Wh,
    const float* __restrict__ bh_n,
    float* __restrict__ out_hidden)
{
    extern __shared__ float sm[];
    float* Wh_s = sm;                    // 128*384 = 49152
    float* h_s  = Wh_s + 49152;          // 4*128   = 512
    float* hh_s = h_s + 512;             // 4*384   = 1536
    float* xn_s = hh_s + 1536;           // 4*128   = 512
    float* bh_s = xn_s + 512;            // 128

    const int tid = threadIdx.x;
    const int rowbase = blockIdx.x * 4;

    for (int i = tid; i < 49152; i += 384) {
        int k = i / cG, c = i % cG;
        Wh_s[(k >> 1) * 768 + c * 2 + (k & 1)] = Wh[i];
    }
    if (tid < 128) bh_s[tid] = bh_n[tid];
    {
        int d0[4];
#pragma unroll
        for (int r = 0; r < 4; r++) d0[r] = dones[rowbase + r];
        for (int i = tid; i < 512; i += 384)
            h_s[i] = (d0[i >> 7] != 0) ? 0.f : h0[rowbase * cH + i];
    }
    __syncthreads();

    for (int t = 0; t < cT; t++) {
        // Prefetch xi for this step + dones for the next
        float xiv[4];
        {
            const float* xp = &g_xi[((size_t)t * cB + rowbase) * cG + tid];
#pragma unroll
            for (int r = 0; r < 4; r++) xiv[r] = xp[(size_t)r * cG];
        }
        int dn[4];
        if (t + 1 < cT) {
#pragma unroll
            for (int r = 0; r < 4; r++) dn[r] = dones[(size_t)(t + 1) * cB + rowbase + r];
        } else {
            dn[0] = dn[1] = dn[2] = dn[3] = 0;
        }

        // hh[r][tid] = sum_k h[r][k] * Wh[k][tid]  via FFMA2 over k-pairs
        ull acc2[4] = {0ull, 0ull, 0ull, 0ull};
#pragma unroll 8
        for (int kp = 0; kp < 64; kp += 2) {
            ulonglong2 ha[4];
#pragma unroll
            for (int r = 0; r < 4; r++)
                ha[r] = *reinterpret_cast<const ulonglong2*>(&h_s[r * 128 + kp * 2]);
            ull w0 = *reinterpret_cast<const ull*>(&Wh_s[kp * 768 + tid * 2]);
            ull w1 = *reinterpret_cast<const ull*>(&Wh_s[(kp + 1) * 768 + tid * 2]);
#pragma unroll
            for (int r = 0; r < 4; r++) ffma2(acc2[r], ha[r].x, w0);
#pragma unroll
            for (int r = 0; r < 4; r++) ffma2(acc2[r], ha[r].y, w1);
        }
        float acc[4];
#pragma unroll
        for (int r = 0; r < 4; r++) acc[r] = f2sum(acc2[r]);

        if (tid < 256) {
#pragma unroll
            for (int r = 0; r < 4; r++) hh_s[r * cG + tid] = acc[r] + xiv[r];
        } else {
            const int m = tid - 256;
#pragma unroll
            for (int r = 0; r < 4; r++) {
                hh_s[r * cG + tid] = acc[r];
                xn_s[r * 128 + m]  = xiv[r];
            }
        }
        __syncthreads();

        for (int i = tid; i < 512; i += 384) {
            const int r = i >> 7, m = i & 127;
            float pre_r = hh_s[r * cG + m];
            float pre_z = hh_s[r * cG + 128 + m];
            float hn    = hh_s[r * cG + 256 + m];
            float rg = 1.f / (1.f + expf(-pre_r));
            float zg = 1.f / (1.f + expf(-pre_z));
            float ng = tanhf(xn_s[r * 128 + m] + rg * (hn + bh_s[m]));
            float hprev = h_s[i];
            float hnew  = (1.f - zg) * ng + zg * hprev;
            g_y[((size_t)t * cB + rowbase + r) * cH + m] = hnew;
            if (t == cT - 1) out_hidden[(rowbase + r) * cH + m] = hnew;
            h_s[i] = (dn[r] != 0) ? 0.f : hnew;
        }
        __syncthreads();
    }
}

// ---------------------------------------------------------------------------
// Kernel 3: actor + critic heads. 128 rows/block, 512 threads, FFMA2.
// ---------------------------------------------------------------------------
__global__ __launch_bounds__(512) void k_heads(
    const float* __restrict__ Wa1, const float* __restrict__ ba1,
    const float* __restrict__ Wa2, const float* __restrict__ ba2,
    const float* __restrict__ Wc1, const float* __restrict__ bc1,
    const float* __restrict__ Wc2, const float* __restrict__ bc2,
    float* __restrict__ out_logits, float* __restrict__ out_v)
{
    extern __shared__ float sm[];
    float* s_y   = sm;                    // 128*128 = 16384
    float* s_w   = s_y + 16384;           // 16384 (interleaved)
    float* s_h   = s_w + 16384;           // 128*132 = 16896 (padded for col scans)
    float* s_w2  = s_h + 16896;           // 128*16  = 2048
    float* s_wc2 = s_w2 + 2048;           // 128

    const int tid  = threadIdx.x;
    const int lane = tid & 31;
    const int wrp  = tid >> 5;
    const int c0   = lane * 4;
    const int r0   = wrp * 8;
    const size_t row0 = (size_t)blockIdx.x * 128;

    for (int i = tid; i < 128 * 128 / 4; i += 512)
        reinterpret_cast<float4*>(s_y)[i] =
            reinterpret_cast<const float4*>(g_y + row0 * cH)[i];
    for (int i = tid; i < 128 * 128; i += 512) {
        int k = i >> 7, c = i & 127;
        s_w[(k >> 1) * 256 + c * 2 + (k & 1)] = Wa1[i];
    }
    for (int i = tid; i < 128 * 16; i += 512) s_w2[i] = Wa2[i];
    if (tid < 128) s_wc2[tid] = Wc2[tid];
    __syncthreads();

    ull acc[8][4];

    // actor layer 1: a1 = relu(y @ Wa1 + ba1)
#pragma unroll
    for (int r = 0; r < 8; r++) { acc[r][0] = acc[r][1] = acc[r][2] = acc[r][3] = 0ull; }
#pragma unroll 8
    for (int kp = 0; kp < 64; kp++) {
        ulonglong2 wA = *reinterpret_cast<const ulonglong2*>(&s_w[kp * 256 + c0 * 2]);
        ulonglong2 wB = *reinterpret_cast<const ulonglong2*>(&s_w[kp * 256 + c0 * 2 + 4]);
#pragma unroll
        for (int r = 0; r < 8; r++) {
            ull a2 = *reinterpret_cast<const ull*>(&s_y[(r0 + r) * 128 + kp * 2]);
            ffma2(acc[r][0], a2, wA.x); ffma2(acc[r][1], a2, wA.y);
            ffma2(acc[r][2], a2, wB.x); ffma2(acc[r][3], a2, wB.y);
        }
    }
    {
        float4 bv = *reinterpret_cast<const float4*>(&ba1[c0]);
#pragma unroll
        for (int r = 0; r < 8; r++) {
            float* d = &s_h[(r0 + r) * 132 + c0];
            d[0] = fmaxf(f2sum(acc[r][0]) + bv.x, 0.f);
            d[1] = fmaxf(f2sum(acc[r][1]) + bv.y, 0.f);
            d[2] = fmaxf(f2sum(acc[r][2]) + bv.z, 0.f);
            d[3] = fmaxf(f2sum(acc[r][3]) + bv.w, 0.f);
        }
    }
    __syncthreads();

    // logits = a1 @ Wa2 + ba2 (thread: 1 row x 4 cols); also restage Wc1
    {
        const int lrow = tid >> 2;
        const int cg   = (tid & 3) * 4;
        float a4[4] = {0.f, 0.f, 0.f, 0.f};
#pragma unroll 4
        for (int k = 0; k < 128; k++) {
            float a  = s_h[lrow * 132 + k];
            float4 w = *reinterpret_cast<const float4*>(&s_w2[k * 16 + cg]);
            a4[0] += a * w.x; a4[1] += a * w.y; a4[2] += a * w.z; a4[3] += a * w.w;
        }
        float4 bv = *reinterpret_cast<const float4*>(&ba2[cg]);
        float4 o;
        o.x = a4[0] + bv.x; o.y = a4[1] + bv.y; o.z = a4[2] + bv.z; o.w = a4[3] + bv.w;
        *reinterpret_cast<float4*>(&out_logits[(row0 + lrow) * cA + cg]) = o;
    }
    for (int i = tid; i < 128 * 128; i += 512) {
        int k = i >> 7, c = i & 127;
        s_w[(k >> 1) * 256 + c * 2 + (k & 1)] = Wc1[i];
    }
    __syncthreads();

    // critic layer 1
#pragma unroll
    for (int r = 0; r < 8; r++) { acc[r][0] = acc[r][1] = acc[r][2] = acc[r][3] = 0ull; }
#pragma unroll 8
    for (int kp = 0; kp < 64; kp++) {
        ulonglong2 wA = *reinterpret_cast<const ulonglong2*>(&s_w[kp * 256 + c0 * 2]);
        ulonglong2 wB = *reinterpret_cast<const ulonglong2*>(&s_w[kp * 256 + c0 * 2 + 4]);
#pragma unroll
        for (int r = 0; r < 8; r++) {
            ull a2 = *reinterpret_cast<const ull*>(&s_y[(r0 + r) * 128 + kp * 2]);
            ffma2(acc[r][0], a2, wA.x); ffma2(acc[r][1], a2, wA.y);
            ffma2(acc[r][2], a2, wB.x); ffma2(acc[r][3], a2, wB.y);
        }
    }
    {
        float4 bv = *reinterpret_cast<const float4*>(&bc1[c0]);
#pragma unroll
        for (int r = 0; r < 8; r++) {
            float* d = &s_h[(r0 + r) * 132 + c0];
            d[0] = fmaxf(f2sum(acc[r][0]) + bv.x, 0.f);
            d[1] = fmaxf(f2sum(acc[r][1]) + bv.y, 0.f);
            d[2] = fmaxf(f2sum(acc[r][2]) + bv.z, 0.f);
            d[3] = fmaxf(f2sum(acc[r][3]) + bv.w, 0.f);
        }
    }
    __syncthreads();

    // value = c1 @ Wc2 + bc2
    if (tid < 128) {
        float a = 0.f;
#pragma unroll 4
        for (int k = 0; k < 128; k++) a += s_h[tid * 132 + k] * s_wc2[k];
        out_v[row0 + tid] = a + bc2[0];
    }
}

// ---------------------------------------------------------------------------
extern "C" void kernel_launch(void* const* d_in, const int* in_sizes, int n_in,
                              void* d_out, int out_size)
{
    const float* hidden = (const float*)d_in[0];
    const float* obs    = (const float*)d_in[1];
    const int*   dones  = (const int*)d_in[2];
    const float* W_emb  = (const float*)d_in[3];
    const float* b_emb  = (const float*)d_in[4];
    const float* Wi     = (const float*)d_in[5];
    const float* bi     = (const float*)d_in[6];
    const float* Wh     = (const float*)d_in[7];
    const float* bh_n   = (const float*)d_in[8];
    const float* Wa1    = (const float*)d_in[9];
    const float* ba1    = (const float*)d_in[10];
    const float* Wa2    = (const float*)d_in[11];
    const float* ba2    = (const float*)d_in[12];
    const float* Wc1    = (const float*)d_in[13];
    const float* bc1    = (const float*)d_in[14];
    const float* Wc2    = (const float*)d_in[15];
    const float* bc2    = (const float*)d_in[16];

    float* out        = (float*)d_out;
    float* out_hidden = out;                                   // [B,H]
    float* out_logits = out + (size_t)cB * cH;                 // [T,B,A]
    float* out_v      = out_logits + (size_t)cTB * cA;         // [T,B]

    const int sm1 = (8192 + 16384 + 16384) * (int)sizeof(float);              // 160 KB
    const int sm2 = (49152 + 512 + 1536 + 512 + 128) * (int)sizeof(float);    // 202.5 KB
    const int sm3 = (16384 + 16384 + 16896 + 2048 + 128) * (int)sizeof(float);// 202.5 KB
    cudaFuncSetAttribute(k_embed_xi, cudaFuncAttributeMaxDynamicSharedMemorySize, sm1);
    cudaFuncSetAttribute(k_scan,     cudaFuncAttributeMaxDynamicSharedMemorySize, sm2);
    cudaFuncSetAttribute(k_heads,    cudaFuncAttributeMaxDynamicSharedMemorySize, sm3);

    k_embed_xi<<<cTB / 128, 512, sm1>>>(obs, W_emb, b_emb, Wi, bi);
    k_scan<<<cB / 4, 384, sm2>>>(hidden, dones, Wh, bh_n, out_hidden);
    k_heads<<<cTB / 128, 512, sm3>>>(Wa1, ba1, Wa2, ba2, Wc1, bc1, Wc2, bc2,
                                     out_logits, out_v);
}

// round 8
// speedup vs baseline: 1.3818x; 1.1206x over previous
#include <cuda_runtime.h>
#include <cuda_bf16.h>
#include <cstdint>
#include <cstddef>

// Problem constants
#define cT   1024
#define cB   512
#define cOBS 64
#define cH   128
#define cA   16
#define cG   384          // 3*H
#define cTB  (cT * cB)    // 524288

typedef unsigned long long ull;

// Scratch (allocations forbidden -> __device__ globals)
__device__ float g_xi[(size_t)cTB * cG];   // [T*B, 384]
__device__ float g_y[(size_t)cTB * cH];    // [T*B, 128]

// ===========================================================================
// Helpers
// ===========================================================================
__device__ __forceinline__ void ffma2(ull& d, ull a, ull b) {
    asm("fma.rn.f32x2 %0, %1, %2, %0;" : "+l"(d) : "l"(a), "l"(b));
}
__device__ __forceinline__ float f2sum(ull v) {
    return __uint_as_float((unsigned)v) + __uint_as_float((unsigned)(v >> 32));
}

// HMMA: D += A(16x16 bf16, row) * B(16x8 bf16, col); fp32 accumulate.
__device__ __forceinline__ void mma16816(float* d, const unsigned* a, const unsigned* b) {
    asm volatile(
        "mma.sync.aligned.m16n8k16.row.col.f32.bf16.bf16.f32 "
        "{%0,%1,%2,%3}, {%4,%5,%6,%7}, {%8,%9}, {%0,%1,%2,%3};"
        : "+f"(d[0]), "+f"(d[1]), "+f"(d[2]), "+f"(d[3])
        : "r"(a[0]), "r"(a[1]), "r"(a[2]), "r"(a[3]), "r"(b[0]), "r"(b[1]));
}

// bf16 hi/lo split of two fp32 -> packed u32 pairs (elem k in lo half, k+1 in hi)
__device__ __forceinline__ void split2(float x0, float x1, unsigned& hi, unsigned& lo) {
    __nv_bfloat16 h0 = __float2bfloat16(x0);
    __nv_bfloat16 h1 = __float2bfloat16(x1);
    __nv_bfloat16 l0 = __float2bfloat16(x0 - __bfloat162float(h0));
    __nv_bfloat16 l1 = __float2bfloat16(x1 - __bfloat162float(h1));
    hi = (unsigned)__bfloat16_as_ushort(h0) | ((unsigned)__bfloat16_as_ushort(h1) << 16);
    lo = (unsigned)__bfloat16_as_ushort(l0) | ((unsigned)__bfloat16_as_ushort(l1) << 16);
}

// Warp GEMM: 32x32 output tile per warp, 3 hi/lo passes, fp32 accum.
// A: row-major [row][k] bf16 stride SA; B: [n][k] bf16 stride SB.
template<int SA, int SB, int KSTEPS>
__device__ __forceinline__ void warp_gemm3(
    const char* __restrict__ smb, int aHi, int aLo, int bHi, int bLo,
    int wm, int wn, int lane, float acc[2][4][4])
{
#pragma unroll
    for (int mt = 0; mt < 2; mt++)
#pragma unroll
        for (int nt = 0; nt < 4; nt++)
#pragma unroll
            for (int j = 0; j < 4; j++) acc[mt][nt][j] = 0.f;

    const int rq = wm * 32 + (lane >> 2);
    const int nq = wn * 32 + (lane >> 2);
    const int kq = (lane & 3) * 2;
#pragma unroll
    for (int p = 0; p < 3; p++) {
        const char* A = smb + (p == 2 ? aLo : aHi);
        const char* B = smb + (p == 1 ? bLo : bHi);
#pragma unroll
        for (int ks = 0; ks < KSTEPS; ks++) {
            const int kb = ks * 16 + kq;
            unsigned a[2][4];
#pragma unroll
            for (int mt = 0; mt < 2; mt++) {
                int r = rq + mt * 16;
                a[mt][0] = *(const unsigned*)(A + (r * SA + kb) * 2);
                a[mt][1] = *(const unsigned*)(A + ((r + 8) * SA + kb) * 2);
                a[mt][2] = *(const unsigned*)(A + (r * SA + kb + 8) * 2);
                a[mt][3] = *(const unsigned*)(A + ((r + 8) * SA + kb + 8) * 2);
            }
            unsigned b[4][2];
#pragma unroll
            for (int nt = 0; nt < 4; nt++) {
                int n = nq + nt * 8;
                b[nt][0] = *(const unsigned*)(B + (n * SB + kb) * 2);
                b[nt][1] = *(const unsigned*)(B + (n * SB + kb + 8) * 2);
            }
#pragma unroll
            for (int mt = 0; mt < 2; mt++)
#pragma unroll
                for (int nt = 0; nt < 4; nt++)
                    mma16816(acc[mt][nt], a[mt], b[nt]);
        }
    }
}

// ===========================================================================
// Kernel 1 (HMMA): emb = relu(obs@We+b); xi = emb@Wi+bi -> g_xi
// 128 rows/block, 512 threads (16 warps, 4x4 warp grid, 32x32/warp).
// ===========================================================================
#define ES_A_HI 0         // obs A tiles [128][72] bf16
#define ES_A_LO 18432
#define ES_B_HI 36864     // weight B tiles [128][136] bf16 (We then Wi chunks)
#define ES_B_LO 71680
#define ES_E_HI 106496    // emb A tiles [128][136] bf16
#define ES_E_LO 141312
#define ES_BEMB 176128    // f32[128]
#define ES_BI   176640    // f32[384]
#define ES_TOT  178176

__global__ __launch_bounds__(512) void k_embed_mma(
    const float* __restrict__ obs, const float* __restrict__ W_emb,
    const float* __restrict__ b_emb, const float* __restrict__ Wi,
    const float* __restrict__ bi)
{
    extern __shared__ char smb[];
    const int tid  = threadIdx.x;
    const int lane = tid & 31;
    const int wid  = tid >> 5;
    const int wm   = wid >> 2, wn = wid & 3;
    const size_t row0 = (size_t)blockIdx.x * 128;

    float* s_bemb = (float*)(smb + ES_BEMB);
    float* s_bi   = (float*)(smb + ES_BI);
    if (tid < 128) s_bemb[tid] = b_emb[tid];
    for (int i = tid; i < 384; i += 512) s_bi[i] = bi[i];

    // stage obs A tiles: 128 rows x 32 k-pairs
    for (int i = tid; i < 4096; i += 512) {
        int row = i >> 5, kp = i & 31;
        float2 v = *(const float2*)(obs + (row0 + row) * cOBS + 2 * kp);
        unsigned h, l; split2(v.x, v.y, h, l);
        *(unsigned*)(smb + ES_A_HI + (row * 72 + 2 * kp) * 2) = h;
        *(unsigned*)(smb + ES_A_LO + (row * 72 + 2 * kp) * 2) = l;
    }
    // stage We^T B tiles: 128 n x 32 k-pairs
    for (int i = tid; i < 4096; i += 512) {
        int n = i & 127, kp = i >> 7;
        unsigned h, l; split2(W_emb[(2 * kp) * cH + n], W_emb[(2 * kp + 1) * cH + n], h, l);
        *(unsigned*)(smb + ES_B_HI + (n * 136 + 2 * kp) * 2) = h;
        *(unsigned*)(smb + ES_B_LO + (n * 136 + 2 * kp) * 2) = l;
    }
    __syncthreads();

    float acc[2][4][4];

    // ---- emb GEMM: K=64 ----
    warp_gemm3<72, 136, 4>(smb, ES_A_HI, ES_A_LO, ES_B_HI, ES_B_LO, wm, wn, lane, acc);

    // epilogue: bias+relu, re-split into emb A tiles (stride 136)
#pragma unroll
    for (int mt = 0; mt < 2; mt++) {
        int r = wm * 32 + mt * 16 + (lane >> 2);
#pragma unroll
        for (int nt = 0; nt < 4; nt++) {
            int C = wn * 32 + nt * 8 + (lane & 3) * 2;
            float b0 = s_bemb[C], b1 = s_bemb[C + 1];
            unsigned h, l;
            split2(fmaxf(acc[mt][nt][0] + b0, 0.f), fmaxf(acc[mt][nt][1] + b1, 0.f), h, l);
            *(unsigned*)(smb + ES_E_HI + (r * 136 + C) * 2) = h;
            *(unsigned*)(smb + ES_E_LO + (r * 136 + C) * 2) = l;
            split2(fmaxf(acc[mt][nt][2] + b0, 0.f), fmaxf(acc[mt][nt][3] + b1, 0.f), h, l);
            *(unsigned*)(smb + ES_E_HI + ((r + 8) * 136 + C) * 2) = h;
            *(unsigned*)(smb + ES_E_LO + ((r + 8) * 136 + C) * 2) = l;
        }
    }

    // ---- xi chunks ----
    for (int c = 0; c < 3; c++) {
        __syncthreads();    // prior GEMM reads + emb writes complete
        for (int i = tid; i < 8192; i += 512) {
            int n = i & 127, kp = i >> 7;
            unsigned h, l;
            split2(Wi[(2 * kp) * cG + c * 128 + n], Wi[(2 * kp + 1) * cG + c * 128 + n], h, l);
            *(unsigned*)(smb + ES_B_HI + (n * 136 + 2 * kp) * 2) = h;
            *(unsigned*)(smb + ES_B_LO + (n * 136 + 2 * kp) * 2) = l;
        }
        __syncthreads();

        warp_gemm3<136, 136, 8>(smb, ES_E_HI, ES_E_LO, ES_B_HI, ES_B_LO, wm, wn, lane, acc);

#pragma unroll
        for (int mt = 0; mt < 2; mt++) {
            int r = wm * 32 + mt * 16 + (lane >> 2);
#pragma unroll
            for (int nt = 0; nt < 4; nt++) {
                int C = wn * 32 + nt * 8 + (lane & 3) * 2;
                float b0 = s_bi[c * 128 + C], b1 = s_bi[c * 128 + C + 1];
                float2 o0 = {acc[mt][nt][0] + b0, acc[mt][nt][1] + b1};
                float2 o1 = {acc[mt][nt][2] + b0, acc[mt][nt][3] + b1};
                *(float2*)(&g_xi[(row0 + r) * cG + c * 128 + C]) = o0;
                *(float2*)(&g_xi[(row0 + r + 8) * cG + c * 128 + C]) = o1;
            }
        }
    }
}

// ===========================================================================
// Kernel 2: GRU scan (unchanged). 128 blocks x 4 rows, FFMA2, Wh in smem.
// ===========================================================================
__global__ __launch_bounds__(384) void k_scan(
    const float* __restrict__ h0,
    const int* __restrict__ dones,
    const float* __restrict__ Wh,
    const float* __restrict__ bh_n,
    float* __restrict__ out_hidden)
{
    extern __shared__ float sm[];
    float* Wh_s = sm;                    // 128*384 = 49152
    float* h_s  = Wh_s + 49152;          // 512
    float* hh_s = h_s + 512;             // 1536
    float* xn_s = hh_s + 1536;           // 512
    float* bh_s = xn_s + 512;            // 128

    const int tid = threadIdx.x;
    const int rowbase = blockIdx.x * 4;

    for (int i = tid; i < 49152; i += 384) {
        int k = i / cG, c = i % cG;
        Wh_s[(k >> 1) * 768 + c * 2 + (k & 1)] = Wh[i];
    }
    if (tid < 128) bh_s[tid] = bh_n[tid];
    {
        int d0[4];
#pragma unroll
        for (int r = 0; r < 4; r++) d0[r] = dones[rowbase + r];
        for (int i = tid; i < 512; i += 384)
            h_s[i] = (d0[i >> 7] != 0) ? 0.f : h0[rowbase * cH + i];
    }
    __syncthreads();

    for (int t = 0; t < cT; t++) {
        float xiv[4];
        {
            const float* xp = &g_xi[((size_t)t * cB + rowbase) * cG + tid];
#pragma unroll
            for (int r = 0; r < 4; r++) xiv[r] = xp[(size_t)r * cG];
        }
        int dn[4];
        if (t + 1 < cT) {
#pragma unroll
            for (int r = 0; r < 4; r++) dn[r] = dones[(size_t)(t + 1) * cB + rowbase + r];
        } else {
            dn[0] = dn[1] = dn[2] = dn[3] = 0;
        }

        ull acc2[4] = {0ull, 0ull, 0ull, 0ull};
#pragma unroll 8
        for (int kp = 0; kp < 64; kp += 2) {
            ulonglong2 ha[4];
#pragma unroll
            for (int r = 0; r < 4; r++)
                ha[r] = *reinterpret_cast<const ulonglong2*>(&h_s[r * 128 + kp * 2]);
            ull w0 = *reinterpret_cast<const ull*>(&Wh_s[kp * 768 + tid * 2]);
            ull w1 = *reinterpret_cast<const ull*>(&Wh_s[(kp + 1) * 768 + tid * 2]);
#pragma unroll
            for (int r = 0; r < 4; r++) ffma2(acc2[r], ha[r].x, w0);
#pragma unroll
            for (int r = 0; r < 4; r++) ffma2(acc2[r], ha[r].y, w1);
        }
        float acc[4];
#pragma unroll
        for (int r = 0; r < 4; r++) acc[r] = f2sum(acc2[r]);

        if (tid < 256) {
#pragma unroll
            for (int r = 0; r < 4; r++) hh_s[r * cG + tid] = acc[r] + xiv[r];
        } else {
            const int m = tid - 256;
#pragma unroll
            for (int r = 0; r < 4; r++) {
                hh_s[r * cG + tid] = acc[r];
                xn_s[r * 128 + m]  = xiv[r];
            }
        }
        __syncthreads();

        for (int i = tid; i < 512; i += 384) {
            const int r = i >> 7, m = i & 127;
            float pre_r = hh_s[r * cG + m];
            float pre_z = hh_s[r * cG + 128 + m];
            float hn    = hh_s[r * cG + 256 + m];
            float rg = 1.f / (1.f + expf(-pre_r));
            float zg = 1.f / (1.f + expf(-pre_z));
            float ng = tanhf(xn_s[r * 128 + m] + rg * (hn + bh_s[m]));
            float hprev = h_s[i];
            float hnew  = (1.f - zg) * ng + zg * hprev;
            g_y[((size_t)t * cB + rowbase + r) * cH + m] = hnew;
            if (t == cT - 1) out_hidden[(rowbase + r) * cH + m] = hnew;
            h_s[i] = (dn[r] != 0) ? 0.f : hnew;
        }
        __syncthreads();
    }
}

// ===========================================================================
// Kernel 3 (HMMA): heads. a1/c1 GEMMs; scalar logits/value epilogue.
// 128 rows/block, 512 threads.
// ===========================================================================
#define HS_AY_HI 0         // y A tiles [128][136] bf16 (c1 f32 aliases after)
#define HS_AY_LO 34816
#define HS_B_HI  69632     // weight B tiles [128][136] (Wa1 then Wc1)
#define HS_B_LO  104448
#define HS_A1F   139264    // f32 [128][132] = 67584
#define HS_WA2   206848    // f32 [128][16]  = 8192
#define HS_WC2   215040    // f32 [128]
#define HS_BA1   215552
#define HS_BC1   216064
#define HS_BA2   216576
#define HS_BC2   216640
#define HS_TOT   216704
#define HS_C1F   0         // f32 [128][132], aliases AY region

__global__ __launch_bounds__(512) void k_heads_mma(
    const float* __restrict__ Wa1, const float* __restrict__ ba1,
    const float* __restrict__ Wa2, const float* __restrict__ ba2,
    const float* __restrict__ Wc1, const float* __restrict__ bc1,
    const float* __restrict__ Wc2, const float* __restrict__ bc2,
    float* __restrict__ out_logits, float* __restrict__ out_v)
{
    extern __shared__ char smb[];
    const int tid  = threadIdx.x;
    const int lane = tid & 31;
    const int wid  = tid >> 5;
    const int wm   = wid >> 2, wn = wid & 3;
    const size_t row0 = (size_t)blockIdx.x * 128;

    float* s_a1  = (float*)(smb + HS_A1F);
    float* s_c1  = (float*)(smb + HS_C1F);
    float* s_wa2 = (float*)(smb + HS_WA2);
    float* s_wc2 = (float*)(smb + HS_WC2);
    float* s_ba1 = (float*)(smb + HS_BA1);
    float* s_bc1 = (float*)(smb + HS_BC1);
    float* s_ba2 = (float*)(smb + HS_BA2);
    float* s_bc2 = (float*)(smb + HS_BC2);

    if (tid < 128) { s_ba1[tid] = ba1[tid]; s_bc1[tid] = bc1[tid]; s_wc2[tid] = Wc2[tid]; }
    if (tid < 16)  s_ba2[tid] = ba2[tid];
    if (tid == 0)  s_bc2[0] = bc2[0];
    for (int i = tid; i < 2048; i += 512) s_wa2[i] = Wa2[i];

    // stage y A tiles: 128 rows x 64 k-pairs
    for (int i = tid; i < 8192; i += 512) {
        int row = i >> 6, kp = i & 63;
        float2 v = *(const float2*)(g_y + (row0 + row) * cH + 2 * kp);
        unsigned h, l; split2(v.x, v.y, h, l);
        *(unsigned*)(smb + HS_AY_HI + (row * 136 + 2 * kp) * 2) = h;
        *(unsigned*)(smb + HS_AY_LO + (row * 136 + 2 * kp) * 2) = l;
    }
    // stage Wa1^T B tiles
    for (int i = tid; i < 8192; i += 512) {
        int n = i & 127, kp = i >> 7;
        unsigned h, l; split2(Wa1[(2 * kp) * cH + n], Wa1[(2 * kp + 1) * cH + n], h, l);
        *(unsigned*)(smb + HS_B_HI + (n * 136 + 2 * kp) * 2) = h;
        *(unsigned*)(smb + HS_B_LO + (n * 136 + 2 * kp) * 2) = l;
    }
    __syncthreads();

    float acc[2][4][4];

    // ---- a1 = relu(y@Wa1 + ba1) -> f32 smem ----
    warp_gemm3<136, 136, 8>(smb, HS_AY_HI, HS_AY_LO, HS_B_HI, HS_B_LO, wm, wn, lane, acc);
#pragma unroll
    for (int mt = 0; mt < 2; mt++) {
        int r = wm * 32 + mt * 16 + (lane >> 2);
#pragma unroll
        for (int nt = 0; nt < 4; nt++) {
            int C = wn * 32 + nt * 8 + (lane & 3) * 2;
            float b0 = s_ba1[C], b1 = s_ba1[C + 1];
            s_a1[r * 132 + C]           = fmaxf(acc[mt][nt][0] + b0, 0.f);
            s_a1[r * 132 + C + 1]       = fmaxf(acc[mt][nt][1] + b1, 0.f);
            s_a1[(r + 8) * 132 + C]     = fmaxf(acc[mt][nt][2] + b0, 0.f);
            s_a1[(r + 8) * 132 + C + 1] = fmaxf(acc[mt][nt][3] + b1, 0.f);
        }
    }
    __syncthreads();

    // restage B <- Wc1
    for (int i = tid; i < 8192; i += 512) {
        int n = i & 127, kp = i >> 7;
        unsigned h, l; split2(Wc1[(2 * kp) * cH + n], Wc1[(2 * kp + 1) * cH + n], h, l);
        *(unsigned*)(smb + HS_B_HI + (n * 136 + 2 * kp) * 2) = h;
        *(unsigned*)(smb + HS_B_LO + (n * 136 + 2 * kp) * 2) = l;
    }
    __syncthreads();

    // ---- c1 = relu(y@Wc1 + bc1) ----
    warp_gemm3<136, 136, 8>(smb, HS_AY_HI, HS_AY_LO, HS_B_HI, HS_B_LO, wm, wn, lane, acc);
    __syncthreads();   // all AY reads done before c1 f32 overwrites the region
#pragma unroll
    for (int mt = 0; mt < 2; mt++) {
        int r = wm * 32 + mt * 16 + (lane >> 2);
#pragma unroll
        for (int nt = 0; nt < 4; nt++) {
            int C = wn * 32 + nt * 8 + (lane & 3) * 2;
            float b0 = s_bc1[C], b1 = s_bc1[C + 1];
            s_c1[r * 132 + C]           = fmaxf(acc[mt][nt][0] + b0, 0.f);
            s_c1[r * 132 + C + 1]       = fmaxf(acc[mt][nt][1] + b1, 0.f);
            s_c1[(r + 8) * 132 + C]     = fmaxf(acc[mt][nt][2] + b0, 0.f);
            s_c1[(r + 8) * 132 + C + 1] = fmaxf(acc[mt][nt][3] + b1, 0.f);
        }
    }
    __syncthreads();

    // ---- logits = a1 @ Wa2 + ba2 (scalar) ----
    {
        const int lrow = tid >> 2;
        const int cg   = (tid & 3) * 4;
        float a4[4] = {0.f, 0.f, 0.f, 0.f};
#pragma unroll 4
        for (int k = 0; k < 128; k++) {
            float a  = s_a1[lrow * 132 + k];
            float4 w = *(const float4*)(&s_wa2[k * 16 + cg]);
            a4[0] += a * w.x; a4[1] += a * w.y; a4[2] += a * w.z; a4[3] += a * w.w;
        }
        float4 o;
        o.x = a4[0] + s_ba2[cg];     o.y = a4[1] + s_ba2[cg + 1];
        o.z = a4[2] + s_ba2[cg + 2]; o.w = a4[3] + s_ba2[cg + 3];
        *(float4*)(&out_logits[(row0 + lrow) * cA + cg]) = o;
    }
    // ---- value = c1 . Wc2 + bc2 ----
    if (tid < 128) {
        float a = 0.f;
#pragma unroll 4
        for (int k = 0; k < 128; k++) a += s_c1[tid * 132 + k] * s_wc2[k];
        out_v[row0 + tid] = a + s_bc2[0];
    }
}

// ---------------------------------------------------------------------------
extern "C" void kernel_launch(void* const* d_in, const int* in_sizes, int n_in,
                              void* d_out, int out_size)
{
    const float* hidden = (const float*)d_in[0];
    const float* obs    = (const float*)d_in[1];
    const int*   dones  = (const int*)d_in[2];
    const float* W_emb  = (const float*)d_in[3];
    const float* b_emb  = (const float*)d_in[4];
    const float* Wi     = (const float*)d_in[5];
    const float* bi     = (const float*)d_in[6];
    const float* Wh     = (const float*)d_in[7];
    const float* bh_n   = (const float*)d_in[8];
    const float* Wa1    = (const float*)d_in[9];
    const float* ba1    = (const float*)d_in[10];
    const float* Wa2    = (const float*)d_in[11];
    const float* ba2    = (const float*)d_in[12];
    const float* Wc1    = (const float*)d_in[13];
    const float* bc1    = (const float*)d_in[14];
    const float* Wc2    = (const float*)d_in[15];
    const float* bc2    = (const float*)d_in[16];

    float* out        = (float*)d_out;
    float* out_hidden = out;                                   // [B,H]
    float* out_logits = out + (size_t)cB * cH;                 // [T,B,A]
    float* out_v      = out_logits + (size_t)cTB * cA;         // [T,B]

    const int sm2 = (49152 + 512 + 1536 + 512 + 128) * (int)sizeof(float);
    cudaFuncSetAttribute(k_embed_mma, cudaFuncAttributeMaxDynamicSharedMemorySize, ES_TOT);
    cudaFuncSetAttribute(k_scan,      cudaFuncAttributeMaxDynamicSharedMemorySize, sm2);
    cudaFuncSetAttribute(k_heads_mma, cudaFuncAttributeMaxDynamicSharedMemorySize, HS_TOT);

    k_embed_mma<<<cTB / 128, 512, ES_TOT>>>(obs, W_emb, b_emb, Wi, bi);
    k_scan<<<cB / 4, 384, sm2>>>(hidden, dones, Wh, bh_n, out_hidden);
    k_heads_mma<<<cTB / 128, 512, HS_TOT>>>(Wa1, ba1, Wa2, ba2, Wc1, bc1, Wc2, bc2,
                                            out_logits, out_v);
}

// round 10
// speedup vs baseline: 1.9501x; 1.4113x over previous
#include <cuda_runtime.h>
#include <cuda_bf16.h>
#include <cstdint>
#include <cstddef>

// Problem constants
#define cT   1024
#define cB   512
#define cOBS 64
#define cH   128
#define cA   16
#define cG   384          // 3*H
#define cTB  (cT * cB)    // 524288

typedef unsigned long long ull;

// Scratch (allocations forbidden -> __device__ globals)
__device__ float g_xi[(size_t)cTB * cG];   // [T*B, 384]
__device__ float g_y[(size_t)cTB * cH];    // [T*B, 128]

// Pre-split weights (bf16 hi/lo, transposed [n][k], k-stride padded to 136)
__device__ __align__(16) __nv_bfloat16 gWe_hi[128 * 136];
__device__ __align__(16) __nv_bfloat16 gWe_lo[128 * 136];
__device__ __align__(16) __nv_bfloat16 gWi_hi[384 * 136];
__device__ __align__(16) __nv_bfloat16 gWi_lo[384 * 136];
__device__ __align__(16) __nv_bfloat16 gWa1_hi[128 * 136];
__device__ __align__(16) __nv_bfloat16 gWa1_lo[128 * 136];
__device__ __align__(16) __nv_bfloat16 gWc1_hi[128 * 136];
__device__ __align__(16) __nv_bfloat16 gWc1_lo[128 * 136];

// ===========================================================================
// Helpers
// ===========================================================================
__device__ __forceinline__ void ffma2(ull& d, ull a, ull b) {
    asm("fma.rn.f32x2 %0, %1, %2, %0;" : "+l"(d) : "l"(a), "l"(b));
}
__device__ __forceinline__ float f2sum(ull v) {
    return __uint_as_float((unsigned)v) + __uint_as_float((unsigned)(v >> 32));
}
__device__ __forceinline__ uint32_t smem_u32(const void* p) {
    uint32_t a;
    asm("{ .reg .u64 t; cvta.to.shared.u64 t, %1; cvt.u32.u64 %0, t; }"
        : "=r"(a) : "l"(p));
    return a;
}
__device__ __forceinline__ void cpa16(uint32_t dst, const void* src) {
    asm volatile("cp.async.ca.shared.global [%0], [%1], 16;" :: "r"(dst), "l"(src) : "memory");
}
__device__ __forceinline__ void cpa_commit() { asm volatile("cp.async.commit_group;" ::: "memory"); }
__device__ __forceinline__ void cpa_wait1()  { asm volatile("cp.async.wait_group 1;" ::: "memory"); }

__device__ __forceinline__ float fsigmoid(float x) {
    float e = __expf(-fmaxf(x, -60.f));
    return __fdividef(1.f, 1.f + e);
}
__device__ __forceinline__ float ftanh_fast(float x) {
    x = fminf(fmaxf(x, -15.f), 15.f);
    float e = __expf(-2.f * x);
    return __fdividef(1.f - e, 1.f + e);
}

// HMMA: D += A(16x16 bf16, row) * B(16x8 bf16, col); fp32 accumulate.
__device__ __forceinline__ void mma16816(float* d, const unsigned* a, const unsigned* b) {
    asm volatile(
        "mma.sync.aligned.m16n8k16.row.col.f32.bf16.bf16.f32 "
        "{%0,%1,%2,%3}, {%4,%5,%6,%7}, {%8,%9}, {%0,%1,%2,%3};"
        : "+f"(d[0]), "+f"(d[1]), "+f"(d[2]), "+f"(d[3])
        : "r"(a[0]), "r"(a[1]), "r"(a[2]), "r"(a[3]), "r"(b[0]), "r"(b[1]));
}

// bf16 hi/lo split of two fp32 -> packed u32 pairs
__device__ __forceinline__ void split2(float x0, float x1, unsigned& hi, unsigned& lo) {
    __nv_bfloat16 h0 = __float2bfloat16(x0);
    __nv_bfloat16 h1 = __float2bfloat16(x1);
    __nv_bfloat16 l0 = __float2bfloat16(x0 - __bfloat162float(h0));
    __nv_bfloat16 l1 = __float2bfloat16(x1 - __bfloat162float(h1));
    hi = (unsigned)__bfloat16_as_ushort(h0) | ((unsigned)__bfloat16_as_ushort(h1) << 16);
    lo = (unsigned)__bfloat16_as_ushort(l0) | ((unsigned)__bfloat16_as_ushort(l1) << 16);
}

// Warp GEMM: 32x32 output tile per warp, 3 hi/lo passes, fp32 accum.
template<int SA, int SB, int KSTEPS>
__device__ __forceinline__ void warp_gemm3(
    const char* __restrict__ smb, int aHi, int aLo, int bHi, int bLo,
    int wm, int wn, int lane, float acc[2][4][4])
{
#pragma unroll
    for (int mt = 0; mt < 2; mt++)
#pragma unroll
        for (int nt = 0; nt < 4; nt++)
#pragma unroll
            for (int j = 0; j < 4; j++) acc[mt][nt][j] = 0.f;

    const int rq = wm * 32 + (lane >> 2);
    const int nq = wn * 32 + (lane >> 2);
    const int kq = (lane & 3) * 2;
#pragma unroll
    for (int p = 0; p < 3; p++) {
        const char* A = smb + (p == 2 ? aLo : aHi);
        const char* B = smb + (p == 1 ? bLo : bHi);
#pragma unroll
        for (int ks = 0; ks < KSTEPS; ks++) {
            const int kb = ks * 16 + kq;
            unsigned a[2][4];
#pragma unroll
            for (int mt = 0; mt < 2; mt++) {
                int r = rq + mt * 16;
                a[mt][0] = *(const unsigned*)(A + (r * SA + kb) * 2);
                a[mt][1] = *(const unsigned*)(A + ((r + 8) * SA + kb) * 2);
                a[mt][2] = *(const unsigned*)(A + (r * SA + kb + 8) * 2);
                a[mt][3] = *(const unsigned*)(A + ((r + 8) * SA + kb + 8) * 2);
            }
            unsigned b[4][2];
#pragma unroll
            for (int nt = 0; nt < 4; nt++) {
                int n = nq + nt * 8;
                b[nt][0] = *(const unsigned*)(B + (n * SB + kb) * 2);
                b[nt][1] = *(const unsigned*)(B + (n * SB + kb + 8) * 2);
            }
#pragma unroll
            for (int mt = 0; mt < 2; mt++)
#pragma unroll
                for (int nt = 0; nt < 4; nt++)
                    mma16816(acc[mt][nt], a[mt], b[nt]);
        }
    }
}

// ===========================================================================
// Kernel 0: one-time weight pre-split/transpose into bf16 hi/lo arrays.
// ===========================================================================
__global__ void k_prep(const float* __restrict__ We, const float* __restrict__ Wi,
                       const float* __restrict__ Wa1, const float* __restrict__ Wc1)
{
    const int stride = gridDim.x * blockDim.x;
    int i0 = blockIdx.x * blockDim.x + threadIdx.x;
    for (int j = i0; j < 128 * 64; j += stride) {
        int n = j >> 6, k = j & 63;
        float v = We[k * cH + n];
        __nv_bfloat16 h = __float2bfloat16(v);
        gWe_hi[n * 136 + k] = h;
        gWe_lo[n * 136 + k] = __float2bfloat16(v - __bfloat162float(h));
    }
    for (int j = i0; j < 384 * 128; j += stride) {
        int n = j >> 7, k = j & 127;
        float v = Wi[k * cG + n];
        __nv_bfloat16 h = __float2bfloat16(v);
        gWi_hi[n * 136 + k] = h;
        gWi_lo[n * 136 + k] = __float2bfloat16(v - __bfloat162float(h));
    }
    for (int j = i0; j < 128 * 128; j += stride) {
        int n = j >> 7, k = j & 127;
        float va = Wa1[k * cH + n];
        __nv_bfloat16 ha = __float2bfloat16(va);
        gWa1_hi[n * 136 + k] = ha;
        gWa1_lo[n * 136 + k] = __float2bfloat16(va - __bfloat162float(ha));
        float vc = Wc1[k * cH + n];
        __nv_bfloat16 hc = __float2bfloat16(vc);
        gWc1_hi[n * 136 + k] = hc;
        gWc1_lo[n * 136 + k] = __float2bfloat16(vc - __bfloat162float(hc));
    }
}

// ===========================================================================
// Kernel 1 (HMMA): emb = relu(obs@We+b); xi = emb@Wi+bi -> g_xi
// ===========================================================================
#define ES_A_HI 0         // obs A tiles [128][72] bf16
#define ES_A_LO 18432
#define ES_B_HI 36864     // weight B tiles [128][136] bf16
#define ES_B_LO 71680
#define ES_E_HI 106496    // emb A tiles [128][136] bf16
#define ES_E_LO 141312
#define ES_BEMB 176128    // f32[128]
#define ES_BI   176640    // f32[384]
#define ES_TOT  178176

__global__ __launch_bounds__(512) void k_embed_mma(
    const float* __restrict__ obs, const float* __restrict__ b_emb,
    const float* __restrict__ bi)
{
    extern __shared__ char smb[];
    const int tid  = threadIdx.x;
    const int lane = tid & 31;
    const int wid  = tid >> 5;
    const int wm   = wid >> 2, wn = wid & 3;
    const size_t row0 = (size_t)blockIdx.x * 128;

    float* s_bemb = (float*)(smb + ES_BEMB);
    float* s_bi   = (float*)(smb + ES_BI);
    if (tid < 128) s_bemb[tid] = b_emb[tid];
    for (int i = tid; i < 384; i += 512) s_bi[i] = bi[i];

    // stage obs A tiles: 128 rows x 32 k-pairs
    for (int i = tid; i < 4096; i += 512) {
        int row = i >> 5, kp = i & 31;
        float2 v = *(const float2*)(obs + (row0 + row) * cOBS + 2 * kp);
        unsigned h, l; split2(v.x, v.y, h, l);
        *(unsigned*)(smb + ES_A_HI + (row * 72 + 2 * kp) * 2) = h;
        *(unsigned*)(smb + ES_A_LO + (row * 72 + 2 * kp) * 2) = l;
    }
    // stage We B tiles: pure copy of pre-split weights
    for (int i = tid; i < 2176; i += 512) {
        ((float4*)(smb + ES_B_HI))[i] = ((const float4*)gWe_hi)[i];
        ((float4*)(smb + ES_B_LO))[i] = ((const float4*)gWe_lo)[i];
    }
    __syncthreads();

    float acc[2][4][4];

    // ---- emb GEMM: K=64 ----
    warp_gemm3<72, 136, 4>(smb, ES_A_HI, ES_A_LO, ES_B_HI, ES_B_LO, wm, wn, lane, acc);

    // epilogue: bias+relu, re-split into emb A tiles (stride 136)
#pragma unroll
    for (int mt = 0; mt < 2; mt++) {
        int r = wm * 32 + mt * 16 + (lane >> 2);
#pragma unroll
        for (int nt = 0; nt < 4; nt++) {
            int C = wn * 32 + nt * 8 + (lane & 3) * 2;
            float b0 = s_bemb[C], b1 = s_bemb[C + 1];
            unsigned h, l;
            split2(fmaxf(acc[mt][nt][0] + b0, 0.f), fmaxf(acc[mt][nt][1] + b1, 0.f), h, l);
            *(unsigned*)(smb + ES_E_HI + (r * 136 + C) * 2) = h;
            *(unsigned*)(smb + ES_E_LO + (r * 136 + C) * 2) = l;
            split2(fmaxf(acc[mt][nt][2] + b0, 0.f), fmaxf(acc[mt][nt][3] + b1, 0.f), h, l);
            *(unsigned*)(smb + ES_E_HI + ((r + 8) * 136 + C) * 2) = h;
            *(unsigned*)(smb + ES_E_LO + ((r + 8) * 136 + C) * 2) = l;
        }
    }

    // ---- xi chunks ----
    for (int c = 0; c < 3; c++) {
        __syncthreads();
        for (int i = tid; i < 2176; i += 512) {
            ((float4*)(smb + ES_B_HI))[i] = ((const float4*)gWi_hi)[c * 2176 + i];
            ((float4*)(smb + ES_B_LO))[i] = ((const float4*)gWi_lo)[c * 2176 + i];
        }
        __syncthreads();

        warp_gemm3<136, 136, 8>(smb, ES_E_HI, ES_E_LO, ES_B_HI, ES_B_LO, wm, wn, lane, acc);

#pragma unroll
        for (int mt = 0; mt < 2; mt++) {
            int r = wm * 32 + mt * 16 + (lane >> 2);
#pragma unroll
            for (int nt = 0; nt < 4; nt++) {
                int C = wn * 32 + nt * 8 + (lane & 3) * 2;
                float b0 = s_bi[c * 128 + C], b1 = s_bi[c * 128 + C + 1];
                float2 o0 = {acc[mt][nt][0] + b0, acc[mt][nt][1] + b1};
                float2 o1 = {acc[mt][nt][2] + b0, acc[mt][nt][3] + b1};
                *(float2*)(&g_xi[(row0 + r) * cG + c * 128 + C]) = o0;
                *(float2*)(&g_xi[(row0 + r + 8) * cG + c * 128 + C]) = o1;
            }
        }
    }
}

// ===========================================================================
// Kernel 2: GRU scan v2 (dn-slot parity FIXED).
// 384 threads = 192 col-pairs x 2 k-halves. Split-k halves h-broadcast wf.
// Slot discipline: data for timestep k lives in buffer k&1.
//   iter t: reads  xi(t)   from buf t&1,  dones(t+1) from slot (t+1)&1
//           writes xi(t+1) into buf (t+1)&1, dones(t+2) into slot t&1
//   -> reads/writes disjoint within an iteration; wait_group 1 guarantees
//      the producing group (iter t-1) completed before its data is read.
// ===========================================================================
#define SC_WH   0          // 49152
#define SC_H    49152      // 512
#define SC_PART 49664      // 2*1536 : [kh][r][col]
#define SC_XI   52736      // 2*1536 : [buf][r*384+col]
#define SC_BH   55808      // 128
#define SC_DN   55936      // 2*4 ints
#define SC_TOTF 55944

__global__ __launch_bounds__(384) void k_scan(
    const float* __restrict__ h0,
    const int* __restrict__ dones,
    const float* __restrict__ Wh,
    const float* __restrict__ bh_n,
    float* __restrict__ out_hidden)
{
    extern __shared__ float sm[];
    float* Wh_s = sm + SC_WH;
    float* h_s  = sm + SC_H;
    float* part = sm + SC_PART;
    float* xi_s = sm + SC_XI;
    float* bh_s = sm + SC_BH;
    int*   dn_s = (int*)(sm + SC_DN);

    const int tid = threadIdx.x;
    const int kh  = tid >= 192;          // k-half
    const int cp  = tid - kh * 192;      // col-pair 0..191
    const int rowbase = blockIdx.x * 4;
    const uint32_t xi_u32 = smem_u32(xi_s);
    const uint32_t dn_u32 = smem_u32(dn_s);

    // stage Wh packed: Wh_s[kp*768 + c*4] = {W[2kp][2c],W[2kp+1][2c],W[2kp][2c+1],W[2kp+1][2c+1]}
    for (int i = tid; i < 64 * 192; i += 384) {
        int kp = i / 192, c = i % 192;
        float2 a = *(const float2*)&Wh[(2 * kp) * cG + 2 * c];
        float2 b = *(const float2*)&Wh[(2 * kp + 1) * cG + 2 * c];
        float4 w = {a.x, b.x, a.y, b.y};
        *(float4*)&Wh_s[kp * 768 + c * 4] = w;
    }
    if (tid < 128) bh_s[tid] = bh_n[tid];
    {
        int d0[4];
#pragma unroll
        for (int r = 0; r < 4; r++) d0[r] = dones[rowbase + r];
        for (int i = tid; i < 512; i += 384)
            h_s[i] = (d0[i >> 7] != 0) ? 0.f : h0[rowbase * cH + i];
    }

    // prologue prefetch: xi(0) -> buf0, dones(1) -> slot 1
    {
        int r = tid / 96, ch = tid % 96;
        cpa16(xi_u32 + (0 * 1536 + r * 384 + ch * 4) * 4,
              &g_xi[((size_t)0 * cB + rowbase + r) * cG + ch * 4]);
        if (tid == 0)
            cpa16(dn_u32 + 1 * 16, &dones[(size_t)1 * cB + rowbase]);
        cpa_commit();
    }
    __syncthreads();

    const int xr = tid / 96, xch = tid % 96;

    for (int t = 0; t < cT; t++) {
        // prefetch xi(t+1) -> buf (t+1)&1, dones(t+2) -> slot (t+2)&1 = t&1
        {
            int tn = (t + 1 < cT) ? t + 1 : cT - 1;
            int td = (t + 2 < cT) ? t + 2 : cT - 1;
            cpa16(xi_u32 + (((t + 1) & 1) * 1536 + xr * 384 + xch * 4) * 4,
                  &g_xi[((size_t)tn * cB + rowbase + xr) * cG + xch * 4]);
            if (tid == 0)
                cpa16(dn_u32 + (t & 1) * 16, &dones[(size_t)td * cB + rowbase]);
            cpa_commit();
        }

        // GEMM: partial dot over own k-half for 2 cols x 4 rows
        ull acc[4][2];
#pragma unroll
        for (int r = 0; r < 4; r++) { acc[r][0] = 0ull; acc[r][1] = 0ull; }

        const int kpb = kh * 32;
#pragma unroll
        for (int q = 0; q < 16; q++) {
            float4 w0 = *(const float4*)&Wh_s[(kpb + 2 * q) * 768 + cp * 4];
            float4 w1 = *(const float4*)&Wh_s[(kpb + 2 * q + 1) * 768 + cp * 4];
            ull w0a = *(const ull*)&w0.x, w0b = *(const ull*)&w0.z;
            ull w1a = *(const ull*)&w1.x, w1b = *(const ull*)&w1.z;
#pragma unroll
            for (int r = 0; r < 4; r++) {
                float4 hv = *(const float4*)&h_s[r * 128 + kh * 64 + q * 4];
                ull h01 = *(const ull*)&hv.x;
                ull h23 = *(const ull*)&hv.z;
                ffma2(acc[r][0], h01, w0a);
                ffma2(acc[r][1], h01, w0b);
                ffma2(acc[r][0], h23, w1a);
                ffma2(acc[r][1], h23, w1b);
            }
        }
#pragma unroll
        for (int r = 0; r < 4; r++) {
            float2 o = {f2sum(acc[r][0]), f2sum(acc[r][1])};
            *(float2*)&part[kh * 1536 + r * 384 + 2 * cp] = o;
        }

        cpa_wait1();
        __syncthreads();

        // gates: 512 items over 384 threads (threads <128 do a second item)
        const int buf  = t & 1;
        const int dbuf = (t + 1) & 1;
        const float* xib = &xi_s[buf * 1536];
#pragma unroll
        for (int pass = 0; pass < 2; pass++) {
            int it = (pass == 0) ? tid : tid + 384;
            if (pass == 1 && tid >= 128) break;
            int r = it >> 7, m = it & 127;
            float pre_r = part[r * 384 + m]       + part[1536 + r * 384 + m]       + xib[r * 384 + m];
            float pre_z = part[r * 384 + 128 + m] + part[1536 + r * 384 + 128 + m] + xib[r * 384 + 128 + m];
            float hn    = part[r * 384 + 256 + m] + part[1536 + r * 384 + 256 + m];
            float xn    = xib[r * 384 + 256 + m];
            float rg = fsigmoid(pre_r);
            float zg = fsigmoid(pre_z);
            float ng = ftanh_fast(xn + rg * (hn + bh_s[m]));
            float hprev = h_s[r * 128 + m];
            float hnew  = (1.f - zg) * ng + zg * hprev;
            g_y[((size_t)t * cB + rowbase + r) * cH + m] = hnew;
            if (t == cT - 1) out_hidden[(rowbase + r) * cH + m] = hnew;
            h_s[r * 128 + m] = (dn_s[dbuf * 4 + r] != 0) ? 0.f : hnew;
        }
        __syncthreads();
    }
}

// ===========================================================================
// Kernel 3 (HMMA): heads.
// ===========================================================================
#define HS_AY_HI 0
#define HS_AY_LO 34816
#define HS_B_HI  69632
#define HS_B_LO  104448
#define HS_A1F   139264
#define HS_WA2   206848
#define HS_WC2   215040
#define HS_BA1   215552
#define HS_BC1   216064
#define HS_BA2   216576
#define HS_BC2   216640
#define HS_TOT   216704
#define HS_C1F   0

__global__ __launch_bounds__(512) void k_heads_mma(
    const float* __restrict__ ba1, const float* __restrict__ Wa2,
    const float* __restrict__ ba2, const float* __restrict__ bc1,
    const float* __restrict__ Wc2, const float* __restrict__ bc2,
    float* __restrict__ out_logits, float* __restrict__ out_v)
{
    extern __shared__ char smb[];
    const int tid  = threadIdx.x;
    const int lane = tid & 31;
    const int wid  = tid >> 5;
    const int wm   = wid >> 2, wn = wid & 3;
    const size_t row0 = (size_t)blockIdx.x * 128;

    float* s_a1  = (float*)(smb + HS_A1F);
    float* s_c1  = (float*)(smb + HS_C1F);
    float* s_wa2 = (float*)(smb + HS_WA2);
    float* s_wc2 = (float*)(smb + HS_WC2);
    float* s_ba1 = (float*)(smb + HS_BA1);
    float* s_bc1 = (float*)(smb + HS_BC1);
    float* s_ba2 = (float*)(smb + HS_BA2);
    float* s_bc2 = (float*)(smb + HS_BC2);

    if (tid < 128) { s_ba1[tid] = ba1[tid]; s_bc1[tid] = bc1[tid]; s_wc2[tid] = Wc2[tid]; }
    if (tid < 16)  s_ba2[tid] = ba2[tid];
    if (tid == 0)  s_bc2[0] = bc2[0];
    for (int i = tid; i < 2048; i += 512) s_wa2[i] = Wa2[i];

    // stage y A tiles
    for (int i = tid; i < 8192; i += 512) {
        int row = i >> 6, kp = i & 63;
        float2 v = *(const float2*)(g_y + (row0 + row) * cH + 2 * kp);
        unsigned h, l; split2(v.x, v.y, h, l);
        *(unsigned*)(smb + HS_AY_HI + (row * 136 + 2 * kp) * 2) = h;
        *(unsigned*)(smb + HS_AY_LO + (row * 136 + 2 * kp) * 2) = l;
    }
    // stage Wa1 B tiles (copy)
    for (int i = tid; i < 2176; i += 512) {
        ((float4*)(smb + HS_B_HI))[i] = ((const float4*)gWa1_hi)[i];
        ((float4*)(smb + HS_B_LO))[i] = ((const float4*)gWa1_lo)[i];
    }
    __syncthreads();

    float acc[2][4][4];

    // ---- a1 = relu(y@Wa1 + ba1) ----
    warp_gemm3<136, 136, 8>(smb, HS_AY_HI, HS_AY_LO, HS_B_HI, HS_B_LO, wm, wn, lane, acc);
#pragma unroll
    for (int mt = 0; mt < 2; mt++) {
        int r = wm * 32 + mt * 16 + (lane >> 2);
#pragma unroll
        for (int nt = 0; nt < 4; nt++) {
            int C = wn * 32 + nt * 8 + (lane & 3) * 2;
            float b0 = s_ba1[C], b1 = s_ba1[C + 1];
            s_a1[r * 132 + C]           = fmaxf(acc[mt][nt][0] + b0, 0.f);
            s_a1[r * 132 + C + 1]       = fmaxf(acc[mt][nt][1] + b1, 0.f);
            s_a1[(r + 8) * 132 + C]     = fmaxf(acc[mt][nt][2] + b0, 0.f);
            s_a1[(r + 8) * 132 + C + 1] = fmaxf(acc[mt][nt][3] + b1, 0.f);
        }
    }
    __syncthreads();

    // restage B <- Wc1 (copy)
    for (int i = tid; i < 2176; i += 512) {
        ((float4*)(smb + HS_B_HI))[i] = ((const float4*)gWc1_hi)[i];
        ((float4*)(smb + HS_B_LO))[i] = ((const float4*)gWc1_lo)[i];
    }
    __syncthreads();

    // ---- c1 = relu(y@Wc1 + bc1) ----
    warp_gemm3<136, 136, 8>(smb, HS_AY_HI, HS_AY_LO, HS_B_HI, HS_B_LO, wm, wn, lane, acc);
    __syncthreads();   // AY reads done before c1 f32 overwrites region
#pragma unroll
    for (int mt = 0; mt < 2; mt++) {
        int r = wm * 32 + mt * 16 + (lane >> 2);
#pragma unroll
        for (int nt = 0; nt < 4; nt++) {
            int C = wn * 32 + nt * 8 + (lane & 3) * 2;
            float b0 = s_bc1[C], b1 = s_bc1[C + 1];
            s_c1[r * 132 + C]           = fmaxf(acc[mt][nt][0] + b0, 0.f);
            s_c1[r * 132 + C + 1]       = fmaxf(acc[mt][nt][1] + b1, 0.f);
            s_c1[(r + 8) * 132 + C]     = fmaxf(acc[mt][nt][2] + b0, 0.f);
            s_c1[(r + 8) * 132 + C + 1] = fmaxf(acc[mt][nt][3] + b1, 0.f);
        }
    }
    __syncthreads();

    // ---- logits = a1 @ Wa2 + ba2 ----
    {
        const int lrow = tid >> 2;
        const int cg   = (tid & 3) * 4;
        float a4[4] = {0.f, 0.f, 0.f, 0.f};
#pragma unroll 4
        for (int k = 0; k < 128; k++) {
            float a  = s_a1[lrow * 132 + k];
            float4 w = *(const float4*)(&s_wa2[k * 16 + cg]);
            a4[0] += a * w.x; a4[1] += a * w.y; a4[2] += a * w.z; a4[3] += a * w.w;
        }
        float4 o;
        o.x = a4[0] + s_ba2[cg];     o.y = a4[1] + s_ba2[cg + 1];
        o.z = a4[2] + s_ba2[cg + 2]; o.w = a4[3] + s_ba2[cg + 3];
        *(float4*)(&out_logits[(row0 + lrow) * cA + cg]) = o;
    }
    // ---- value = c1 . Wc2 + bc2 ----
    if (tid < 128) {
        float a = 0.f;
#pragma unroll 4
        for (int k = 0; k < 128; k++) a += s_c1[tid * 132 + k] * s_wc2[k];
        out_v[row0 + tid] = a + s_bc2[0];
    }
}

// ---------------------------------------------------------------------------
extern "C" void kernel_launch(void* const* d_in, const int* in_sizes, int n_in,
                              void* d_out, int out_size)
{
    const float* hidden = (const float*)d_in[0];
    const float* obs    = (const float*)d_in[1];
    const int*   dones  = (const int*)d_in[2];
    const float* W_emb  = (const float*)d_in[3];
    const float* b_emb  = (const float*)d_in[4];
    const float* Wi     = (const float*)d_in[5];
    const float* bi     = (const float*)d_in[6];
    const float* Wh     = (const float*)d_in[7];
    const float* bh_n   = (const float*)d_in[8];
    const float* Wa1    = (const float*)d_in[9];
    const float* ba1    = (const float*)d_in[10];
    const float* Wa2    = (const float*)d_in[11];
    const float* ba2    = (const float*)d_in[12];
    const float* Wc1    = (const float*)d_in[13];
    const float* bc1    = (const float*)d_in[14];
    const float* Wc2    = (const float*)d_in[15];
    const float* bc2    = (const float*)d_in[16];

    float* out        = (float*)d_out;
    float* out_hidden = out;                                   // [B,H]
    float* out_logits = out + (size_t)cB * cH;                 // [T,B,A]
    float* out_v      = out_logits + (size_t)cTB * cA;         // [T,B]

    const int smSc = SC_TOTF * (int)sizeof(float);
    cudaFuncSetAttribute(k_embed_mma, cudaFuncAttributeMaxDynamicSharedMemorySize, ES_TOT);
    cudaFuncSetAttribute(k_scan,      cudaFuncAttributeMaxDynamicSharedMemorySize, smSc);
    cudaFuncSetAttribute(k_heads_mma, cudaFuncAttributeMaxDynamicSharedMemorySize, HS_TOT);

    k_prep<<<148, 256>>>(W_emb, Wi, Wa1, Wc1);
    k_embed_mma<<<cTB / 128, 512, ES_TOT>>>(obs, b_emb, bi);
    k_scan<<<cB / 4, 384, smSc>>>(hidden, dones, Wh, bh_n, out_hidden);
    k_heads_mma<<<cTB / 128, 512, HS_TOT>>>(ba1, Wa2, ba2, bc1, Wc2, bc2,
                                            out_logits, out_v);
}